// round 11
// baseline (speedup 1.0000x reference)
#include <cuda_runtime.h>
#include <math.h>
#include <stdint.h>

#define T_LEN  2048
#define B_SZ   32
#define IN_SZ  256
#define H_SZ   512
#define OUT_SZ 256
#define DT_C   0.1f

#define RGROUPS 32
#define BGROUPS 4
#define NCTA    128
#define RPC     16
#define OPC     8
#define BPC     8
#define NTHR    512

// Pitches (floats), %4==0 and ==4 (mod 32)
#define P0  772
#define P1  1028
#define POW 516
#define PX  260    // sX: x(t)
#define PH  1028   // sH: 512 h0 | 512 h1
#define RW  17     // reduced partial width (16 + pad)

#define SMEM_FLOATS (RPC*P0 + RPC*P1 + OPC*POW + BPC*PX + BPC*PH + 128*RW + 128*RW + 64*RW + 72)
#define SMEM_BYTES  (SMEM_FLOATS * 4)

typedef unsigned long long ull;

__device__ float g_h0[2][B_SZ][H_SZ];
__device__ float g_h1[2][B_SZ][H_SZ];
__device__ __align__(128) unsigned g_flag[BGROUPS][32];

__global__ void init_state_kernel() {
    int i = blockIdx.x * blockDim.x + threadIdx.x;
    const int n = 2 * B_SZ * H_SZ;
    if (i < n) {
        ((float*)g_h0)[i] = 0.0f;
        ((float*)g_h1)[i] = 0.0f;
    }
    if (i < BGROUPS * 32) ((unsigned*)g_flag)[i] = 0u;
}

__device__ __forceinline__ void cpa16(uint32_t dst, const void* src) {
    asm volatile("cp.async.cg.shared.global [%0], [%1], 16;"
                 :: "r"(dst), "l"(src) : "memory");
}
#define CP_COMMIT() asm volatile("cp.async.commit_group;" ::: "memory")
#define CP_WAIT(n)  asm volatile("cp.async.wait_group %0;" :: "n"(n) : "memory")

// stage one h-vector set (8 batches x 512 floats): 512 threads x 2 cpa16
template<int COFF>
__device__ __forceinline__ void stage_h2(uint32_t uH, const float* __restrict__ g,
                                         int b0, int bb, int c) {
#pragma unroll
    for (int q = 0; q < 2; q++) {
        cpa16(uH + (bb * PH + COFF + c + q * 256) * 4,
              &g[(size_t)(b0 + bb) * H_SZ + c + q * 256]);
    }
}

// --- pod barrier: per-CTA flag slots; warp0 spins, block joins via sync ---
__device__ __forceinline__ void pod_arrive(unsigned* flg, int rg, unsigned ph) {
    if (threadIdx.x == 0) {
        __threadfence();   // release
        asm volatile("st.relaxed.gpu.global.u32 [%0], %1;"
                     :: "l"(flg + rg), "r"(ph) : "memory");
    }
}
__device__ __forceinline__ void pod_spin_w0(const unsigned* flg, unsigned ph) {
    if (threadIdx.x < 32) {
        unsigned v;
        do {
            asm volatile("ld.acquire.gpu.global.u32 %0, [%1];"
                         : "=r"(v) : "l"(flg + threadIdx.x) : "memory");
        } while (__any_sync(0xffffffffu, v < ph));
    }
}

// packed dual-fp32 FMA (FFMA2)
__device__ __forceinline__ void fmax2(ull& d, ull a, ull b) {
    asm("fma.rn.f32x2 %0, %1, %2, %0;" : "+l"(d) : "l"(a), "l"(b));
}
__device__ __forceinline__ float x2sum(ull v) {
    float lo, hi;
    asm("mov.b64 {%0,%1}, %2;" : "=f"(lo), "=f"(hi) : "l"(v));
    return lo + hi;
}

template<int NIT, int KSTEP, int PW, int PAcc>
__device__ __forceinline__ void mm44p2(const float* __restrict__ sW, int rbase, int wk,
                                       const float* __restrict__ sAct, int bbase, int ak,
                                       ull acc[4][4]) {
#pragma unroll
    for (int it = 0; it < NIT; ++it) {
        ulonglong2 w[4], a[4];
#pragma unroll
        for (int i = 0; i < 4; i++)
            w[i] = *(const ulonglong2*)(sW + (rbase + i) * PW + wk + it * KSTEP);
#pragma unroll
        for (int j = 0; j < 4; j++)
            a[j] = *(const ulonglong2*)(sAct + (bbase + j) * PAcc + ak + it * KSTEP);
#pragma unroll
        for (int i = 0; i < 4; i++)
#pragma unroll
            for (int j = 0; j < 4; j++) {
                fmax2(acc[i][j], w[i].x, a[j].x);
                fmax2(acc[i][j], w[i].y, a[j].y);
            }
    }
}

// A/B partial fold: butterfly over in-warp k-lanes (tid bits 3,4) then store width-16
__device__ __forceinline__ void red_store_ab(float* sRed, ull acc[4][4],
                                             int rt, int bt, int wrp, int tid) {
#pragma unroll
    for (int i = 0; i < 4; i++)
#pragma unroll
        for (int j = 0; j < 4; j++) {
            float v = x2sum(acc[i][j]);
            v += __shfl_xor_sync(0xffffffffu, v, 8);
            v += __shfl_xor_sync(0xffffffffu, v, 16);
            if ((tid & 24) == 0)
                sRed[(64 * bt + 16 * j + 4 * rt + i) * RW + wrp] = v;
        }
}
// C partial fold: butterfly over tid bits 2,3,4
__device__ __forceinline__ void red_store_c(float* sRedC, ull acc[4][4],
                                            int rtC, int btC, int wrp, int tid) {
#pragma unroll
    for (int i = 0; i < 4; i++)
#pragma unroll
        for (int j = 0; j < 4; j++) {
            float v = x2sum(acc[i][j]);
            v += __shfl_xor_sync(0xffffffffu, v, 4);
            v += __shfl_xor_sync(0xffffffffu, v, 8);
            v += __shfl_xor_sync(0xffffffffu, v, 16);
            if ((tid & 28) == 0)
                sRedC[(8 * (4 * btC + j) + 4 * rtC + i) * RW + wrp] = v;
        }
}

__device__ __forceinline__ float sum16(const float* p) {
    float s0 = 0.f, s1 = 0.f, s2 = 0.f, s3 = 0.f;
#pragma unroll
    for (int kk = 0; kk < 16; kk += 4) {
        s0 += p[kk]; s1 += p[kk + 1]; s2 += p[kk + 2]; s3 += p[kk + 3];
    }
    return (s0 + s1) + (s2 + s3);
}

__global__ void __launch_bounds__(NTHR, 1)
rnn_persistent(const float* __restrict__ x,
               const float* __restrict__ Win0, const float* __restrict__ bin0,
               const float* __restrict__ Wrec0, const float* __restrict__ tau0,
               const float* __restrict__ Win1, const float* __restrict__ bin1,
               const float* __restrict__ Wrec1, const float* __restrict__ tau1,
               const float* __restrict__ Wout, const float* __restrict__ bout,
               float* __restrict__ out)
{
    extern __shared__ float sm[];
    float* sW0   = sm;                   // [16][P0]
    float* sW1   = sW0 + RPC * P0;       // [16][P1]
    float* sWo   = sW1 + RPC * P1;       // [8][POW]
    float* sX    = sWo + OPC * POW;      // [8][PX]   x(t)
    float* sH    = sX  + BPC * PX;       // [8][PH]   h0(t-1) | h1(t-2)
    float* sRedA = sH  + BPC * PH;       // 128*RW
    float* sRedB = sRedA + 128 * RW;     // 128*RW
    float* sRedC = sRedB + 128 * RW;     // 64*RW
    float* sBi0  = sRedC + 64 * RW;
    float* sIT0  = sBi0 + RPC;
    float* sBi1  = sIT0 + RPC;
    float* sIT1  = sBi1 + RPC;
    float* sBo   = sIT1 + RPC;

    const int tid = threadIdx.x;
    const int rg  = blockIdx.x & (RGROUPS - 1);
    const int bg  = blockIdx.x >> 5;
    const int b0  = bg * BPC;
    const int r0  = rg * RPC;
    const int o0  = rg * OPC;
    unsigned* flg = g_flag[bg];

    const uint32_t uX = (uint32_t)__cvta_generic_to_shared(sX);
    const uint32_t uH = (uint32_t)__cvta_generic_to_shared(sH);

    const int st_bb = tid >> 6;            // 0..7
    const int st_c  = (tid & 63) * 4;      // 0..252

    // ---- Prologue staging: x(0) [grp X], h0(-1)|h1(-1) zeros [grp H] ----
    cpa16(uX + (st_bb * PX + st_c) * 4,
          &x[((size_t)(b0 + st_bb) * T_LEN + 0) * IN_SZ + st_c]);
    CP_COMMIT();
    stage_h2<0>(uH, &g_h0[1][0][0], b0, st_bb, st_c);
    stage_h2<512>(uH, &g_h1[1][0][0], b0, st_bb, st_c);
    CP_COMMIT();

    // ---- Weights into SMEM (once) ----
    for (int idx = tid; idx < RPC * 768; idx += NTHR) {
        int r = idx / 768, c = idx % 768;
        float v = (c < IN_SZ) ? Win0[(r0 + r) * IN_SZ + c]
                              : Wrec0[(r0 + r) * H_SZ + (c - IN_SZ)];
        sW0[r * P0 + c] = v;
    }
    for (int idx = tid; idx < RPC * 1024; idx += NTHR) {
        int r = idx >> 10, c = idx & 1023;
        float v = (c < H_SZ) ? Win1[(r0 + r) * H_SZ + c]
                             : Wrec1[(r0 + r) * H_SZ + (c - H_SZ)];
        sW1[r * P1 + c] = v;
    }
    for (int idx = tid; idx < OPC * H_SZ; idx += NTHR) {
        int r = idx >> 9, c = idx & 511;
        sWo[r * POW + c] = Wout[(o0 + r) * H_SZ + c];
    }
    if (tid < RPC) {
        sBi0[tid] = bin0[r0 + tid];
        float tc = fminf(fmaxf(tau0[r0 + tid], 0.1f), 10.f);
        sIT0[tid] = DT_C / tc;
        sBi1[tid] = bin1[r0 + tid];
        tc = fminf(fmaxf(tau1[r0 + tid], 0.1f), 10.f);
        sIT1[tid] = DT_C / tc;
    }
    if (tid < OPC) sBo[tid] = bout[o0 + tid];

    // A/B decode: bits[0:1]=rt, bit2=bt, bits[3:4]=ksl (in-warp), bits[5:8]=wrp
    const int rt    = tid & 3;
    const int bt    = (tid >> 2) & 1;
    const int ksl   = (tid >> 3) & 3;
    const int wrp   = tid >> 5;          // 0..15
    const int rbase = rt * 4;
    const int bbase = bt * 4;
    // k bases (in-warp stride 4 floats for conflict-free a-loads)
    const int kxA = wrp * 16 + ksl * 4;  // A x-part: 1 iter, covers 256
    const int khA = wrp * 32 + ksl * 4;  // A h-part: 2 iters step 16, covers 512
    const int kB  = wrp * 64 + ksl * 4;  // B: 4 iters step 16, covers 1024
    // C decode: bit0=rtC, bit1=btC, bits[2:4]=in-warp k
    const int rtC = tid & 1, btC = (tid >> 1) & 1;
    const int kC  = wrp * 32 + ((tid >> 2) & 7) * 4;  // 1 iter, covers 512

    // ===================== main loop: one barrier per step ====================
    // step t: A(t) -> h0(t),  B(t-1) -> h1(t-1),  C(t-2) -> out(t-2)
    for (int t = 0; t < T_LEN; t++) {
        const int s0i = t & 1;
        const int s1i = s0i ^ 1;

        // (1) x(t) landed
        CP_WAIT(1);
        __syncthreads();

        // (2) A-x GEMM while h group may fly
        ull accA[4][4] = {};
        mm44p2<1, 16, P0, PX>(sW0, rbase, kxA, sX, bbase, kxA, accA);

        // (3) h group landed
        CP_WAIT(0);
        __syncthreads();

        // (4) A-h GEMM, fold+store
        mm44p2<2, 16, P0, PH>(sW0, rbase, 256 + khA, sH, bbase, khA, accA);
        red_store_ab(sRedA, accA, rt, bt, wrp, tid);
        __syncthreads();

        // (5) A-reduce (warps 0-3) -> g_h0; all warps: B GEMM into sRedB
        if (tid < 128) {
            float sum = sum16(&sRedA[tid * RW]) + sBi0[tid & 15];
            float tgt = tanhf(sum);
            float hold = sH[(tid >> 4) * PH + r0 + (tid & 15)];        // h0(t-1)
            g_h0[s0i][b0 + (tid >> 4)][r0 + (tid & 15)] = hold + (tgt - hold) * sIT0[tid & 15];
        }
        {
            ull accB[4][4] = {};
            mm44p2<4, 16, P1, PH>(sW1, rbase, kB, sH, bbase, kB, accB);
            red_store_ab(sRedB, accB, rt, bt, wrp, tid);
        }
        __syncthreads();

        // (6) B-reduce (warps 0-3, skip t=0) -> g_h1; all warps: C(t-2) GEMM
        if (t && tid < 128) {
            float sum = sum16(&sRedB[tid * RW]) + sBi1[tid & 15];
            float tgt = tanhf(sum);
            float hold = sH[(tid >> 4) * PH + 512 + r0 + (tid & 15)];  // h1(t-2)
            g_h1[s1i][b0 + (tid >> 4)][r0 + (tid & 15)] = hold + (tgt - hold) * sIT1[tid & 15];
        }
        if (t >= 2) {
            ull accC[4][4] = {};
            mm44p2<1, 16, POW, PH>(sWo, rtC * 4, kC, sH, btC * 4, 512 + kC, accC);
            red_store_c(sRedC, accC, rtC, btC, wrp, tid);
        }
        __syncthreads();

        // (7) publish h0(t), h1(t-1); emit out(t-2) while warp0 spins
        pod_arrive(flg, rg, (unsigned)(t + 1));
        if (t >= 2 && tid >= 128 && tid < 192) {
            const int rw = tid - 128;
            const int cb = rw >> 3, co = rw & 7;
            float res = __ldg(&x[((size_t)(b0 + cb) * T_LEN + (t - 2)) * IN_SZ + o0 + co]);
            out[((size_t)(b0 + cb) * T_LEN + (t - 2)) * OUT_SZ + o0 + co]
                = sum16(&sRedC[rw * RW]) + sBo[co] + res;
        }
        pod_spin_w0(flg, (unsigned)(t + 1));
        __syncthreads();

        // (8) stage x(t+1) [grp X], h0(t)|h1(t-1) [grp H]
        if (t + 1 < T_LEN) {
            cpa16(uX + (st_bb * PX + st_c) * 4,
                  &x[((size_t)(b0 + st_bb) * T_LEN + (t + 1)) * IN_SZ + st_c]);
        }
        CP_COMMIT();
        stage_h2<0>(uH, &g_h0[s0i][0][0], b0, st_bb, st_c);
        stage_h2<512>(uH, &g_h1[s1i][0][0], b0, st_bb, st_c);
        CP_COMMIT();
    }

    // ===== Epilogue: B(T-1) -> h1(T-1); C(T-2); C(T-1) =====
    CP_WAIT(0);
    __syncthreads();                                     // sH = h0(T-1), h1(T-2)
    {
        ull accB[4][4] = {};
        mm44p2<4, 16, P1, PH>(sW1, rbase, kB, sH, bbase, kB, accB);
        red_store_ab(sRedB, accB, rt, bt, wrp, tid);
    }
    __syncthreads();
    if (tid < 128) {
        float sum = sum16(&sRedB[tid * RW]) + sBi1[tid & 15];
        float tgt = tanhf(sum);
        float hold = sH[(tid >> 4) * PH + 512 + r0 + (tid & 15)];      // h1(T-2)
        g_h1[(T_LEN - 1) & 1][b0 + (tid >> 4)][r0 + (tid & 15)]
            = hold + (tgt - hold) * sIT1[tid & 15];
    }
    {
        ull accC[4][4] = {};                             // C(T-2)
        mm44p2<1, 16, POW, PH>(sWo, rtC * 4, kC, sH, btC * 4, 512 + kC, accC);
        red_store_c(sRedC, accC, rtC, btC, wrp, tid);
    }
    __syncthreads();
    pod_arrive(flg, rg, (unsigned)(T_LEN + 1));
    if (tid >= 128 && tid < 192) {
        const int rw = tid - 128;
        const int cb = rw >> 3, co = rw & 7;
        float res = __ldg(&x[((size_t)(b0 + cb) * T_LEN + (T_LEN - 2)) * IN_SZ + o0 + co]);
        out[((size_t)(b0 + cb) * T_LEN + (T_LEN - 2)) * OUT_SZ + o0 + co]
            = sum16(&sRedC[rw * RW]) + sBo[co] + res;
    }
    pod_spin_w0(flg, (unsigned)(T_LEN + 1));
    __syncthreads();

    // stage h1(T-1); C(T-1)
    stage_h2<512>(uH, &g_h1[(T_LEN - 1) & 1][0][0], b0, st_bb, st_c);
    CP_COMMIT();
    CP_WAIT(0);
    __syncthreads();
    {
        ull accC[4][4] = {};
        mm44p2<1, 16, POW, PH>(sWo, rtC * 4, kC, sH, btC * 4, 512 + kC, accC);
        red_store_c(sRedC, accC, rtC, btC, wrp, tid);
    }
    __syncthreads();
    if (tid < 64) {
        const int eb = tid >> 3, eo = tid & 7;
        float res = __ldg(&x[((size_t)(b0 + eb) * T_LEN + (T_LEN - 1)) * IN_SZ + o0 + eo]);
        out[((size_t)(b0 + eb) * T_LEN + (T_LEN - 1)) * OUT_SZ + o0 + eo]
            = sum16(&sRedC[tid * RW]) + sBo[eo] + res;
    }
}

extern "C" void kernel_launch(void* const* d_in, const int* in_sizes, int n_in,
                              void* d_out, int out_size) {
    const float* x     = (const float*)d_in[0];
    const float* Win0  = (const float*)d_in[1];
    const float* bin0  = (const float*)d_in[2];
    const float* Wrec0 = (const float*)d_in[3];
    const float* tau0  = (const float*)d_in[4];
    const float* Win1  = (const float*)d_in[5];
    const float* bin1  = (const float*)d_in[6];
    const float* Wrec1 = (const float*)d_in[7];
    const float* tau1  = (const float*)d_in[8];
    const float* Wout  = (const float*)d_in[9];
    const float* bout  = (const float*)d_in[10];
    float* outp        = (float*)d_out;

    cudaFuncSetAttribute(rnn_persistent,
                         cudaFuncAttributeMaxDynamicSharedMemorySize, SMEM_BYTES);

    init_state_kernel<<<128, 256>>>();
    rnn_persistent<<<NCTA, NTHR, SMEM_BYTES>>>(x, Win0, bin0, Wrec0, tau0,
                                               Win1, bin1, Wrec1, tau1,
                                               Wout, bout, outp);
}

// round 13
// speedup vs baseline: 1.8498x; 1.8498x over previous
#include <cuda_runtime.h>
#include <math.h>
#include <stdint.h>

#define T_LEN  2048
#define B_SZ   32
#define IN_SZ  256
#define H_SZ   512
#define OUT_SZ 256
#define DT_C   0.1f

#define RGROUPS 32
#define BGROUPS 4
#define NCTA    128
#define RPC     16
#define OPC     8
#define BPC     8
#define NTHR    256

// Pitches (floats), %4==0 and ==4 (mod 32)
#define P0  772
#define P1  1028
#define POW 516
#define PX  260    // per x slot
#define PH  1028   // sH: 512 h0 | 512 h1

#define SMEM_FLOATS (RPC*P0 + RPC*P1 + OPC*POW + 2*BPC*PX + BPC*PH + 4224 + 4224 + 4160 + 72)
#define SMEM_BYTES  (SMEM_FLOATS * 4)

typedef unsigned long long ull;

__device__ float g_h0[2][B_SZ][H_SZ];
__device__ float g_h1[2][B_SZ][H_SZ];
__device__ __align__(128) unsigned g_flag[BGROUPS][2][32];  // [pod][flag0|flag1][cta]

__global__ void init_state_kernel() {
    int i = blockIdx.x * blockDim.x + threadIdx.x;
    const int n = 2 * B_SZ * H_SZ;
    if (i < n) {
        ((float*)g_h0)[i] = 0.0f;
        ((float*)g_h1)[i] = 0.0f;
    }
    if (i < BGROUPS * 2 * 32) ((unsigned*)g_flag)[i] = 0u;
}

__device__ __forceinline__ void cpa16(uint32_t dst, const void* src) {
    asm volatile("cp.async.cg.shared.global [%0], [%1], 16;"
                 :: "r"(dst), "l"(src) : "memory");
}
#define CP_COMMIT() asm volatile("cp.async.commit_group;" ::: "memory")
#define CP_WAIT(n)  asm volatile("cp.async.wait_group %0;" :: "n"(n) : "memory")

template<int COFF>
__device__ __forceinline__ void stage_h(uint32_t uH, const float* __restrict__ g,
                                        int b0, int bb, int c) {
#pragma unroll
    for (int q = 0; q < 4; q++) {
        cpa16(uH + (bb * PH + COFF + c + q * 128) * 4,
              &g[(size_t)(b0 + bb) * H_SZ + c + q * 128]);
    }
}
__device__ __forceinline__ void stage_x(uint32_t uXs, const float* __restrict__ xg,
                                        int b0, int t, int bb, int c) {
    cpa16(uXs + (bb * PX + c) * 4,
          &xg[((size_t)(b0 + bb) * T_LEN + t) * IN_SZ + c]);
    cpa16(uXs + (bb * PX + c + 128) * 4,
          &xg[((size_t)(b0 + bb) * T_LEN + t) * IN_SZ + c + 128]);
}

// --- pod barrier: per-CTA flag slots; warp0 spins, block joins via sync ---
__device__ __forceinline__ void pod_arrive(unsigned* flg, int rg, unsigned ph) {
    if (threadIdx.x == 0) {
        __threadfence();   // release: orders all block threads' prior STGs
        asm volatile("st.relaxed.gpu.global.u32 [%0], %1;"
                     :: "l"(flg + rg), "r"(ph) : "memory");
    }
}
__device__ __forceinline__ void pod_spin_w0(const unsigned* flg, unsigned ph) {
    if (threadIdx.x < 32) {
        unsigned v;
        do {
            asm volatile("ld.acquire.gpu.global.u32 %0, [%1];"
                         : "=r"(v) : "l"(flg + threadIdx.x) : "memory");
        } while (__any_sync(0xffffffffu, v < ph));
    }
}

// packed dual-fp32 FMA (FFMA2)
__device__ __forceinline__ void fmax2(ull& d, ull a, ull b) {
    asm("fma.rn.f32x2 %0, %1, %2, %0;" : "+l"(d) : "l"(a), "l"(b));
}
__device__ __forceinline__ float x2sum(ull v) {
    float lo, hi;
    asm("mov.b64 {%0,%1}, %2;" : "=f"(lo), "=f"(hi) : "l"(v));
    return lo + hi;
}

template<int NIT, int KSTEP, int PW, int PAcc>
__device__ __forceinline__ void mm44p2(const float* __restrict__ sW, int rbase, int wk,
                                       const float* __restrict__ sAct, int bbase, int ak,
                                       ull acc[4][4]) {
#pragma unroll
    for (int it = 0; it < NIT; ++it) {
        ulonglong2 w[4], a[4];
#pragma unroll
        for (int i = 0; i < 4; i++)
            w[i] = *(const ulonglong2*)(sW + (rbase + i) * PW + wk + it * KSTEP);
#pragma unroll
        for (int j = 0; j < 4; j++)
            a[j] = *(const ulonglong2*)(sAct + (bbase + j) * PAcc + ak + it * KSTEP);
#pragma unroll
        for (int i = 0; i < 4; i++)
#pragma unroll
            for (int j = 0; j < 4; j++) {
                fmax2(acc[i][j], w[i].x, a[j].x);
                fmax2(acc[i][j], w[i].y, a[j].y);
            }
    }
}

__device__ __forceinline__ float sum32(const float* p) {
    float s0 = 0.f, s1 = 0.f, s2 = 0.f, s3 = 0.f;
#pragma unroll
    for (int kk = 0; kk < 32; kk += 4) {
        s0 += p[kk]; s1 += p[kk + 1]; s2 += p[kk + 2]; s3 += p[kk + 3];
    }
    return (s0 + s1) + (s2 + s3);
}
__device__ __forceinline__ float sum64(const float* p) {
    float s0 = 0.f, s1 = 0.f, s2 = 0.f, s3 = 0.f;
#pragma unroll
    for (int kk = 0; kk < 64; kk += 4) {
        s0 += p[kk]; s1 += p[kk + 1]; s2 += p[kk + 2]; s3 += p[kk + 3];
    }
    return (s0 + s1) + (s2 + s3);
}

__global__ void __launch_bounds__(NTHR, 1)
rnn_persistent(const float* __restrict__ x,
               const float* __restrict__ Win0, const float* __restrict__ bin0,
               const float* __restrict__ Wrec0, const float* __restrict__ tau0,
               const float* __restrict__ Win1, const float* __restrict__ bin1,
               const float* __restrict__ Wrec1, const float* __restrict__ tau1,
               const float* __restrict__ Wout, const float* __restrict__ bout,
               float* __restrict__ out)
{
    extern __shared__ float sm[];
    float* sW0   = sm;                   // [16][P0]
    float* sW1   = sW0 + RPC * P0;       // [16][P1]
    float* sWo   = sW1 + RPC * P1;       // [8][POW]
    float* sX0   = sWo + OPC * POW;      // [8][PX]  x slot 0 (even t)
    float* sX1   = sX0 + BPC * PX;       // [8][PX]  x slot 1 (odd t)
    float* sH    = sX1 + BPC * PX;       // [8][PH]  h0(t-1) | h1(t-2)
    float* sRedA = sH  + BPC * PH;       // 128*33
    float* sRedB = sRedA + 4224;         // 128*33
    float* sRedC = sRedB + 4224;         // 64*65 (own buffer)
    float* sBi0  = sRedC + 4160;
    float* sIT0  = sBi0 + RPC;
    float* sBi1  = sIT0 + RPC;
    float* sIT1  = sBi1 + RPC;
    float* sBo   = sIT1 + RPC;

    const int tid = threadIdx.x;
    const int rg  = blockIdx.x & (RGROUPS - 1);
    const int bg  = blockIdx.x >> 5;
    const int b0  = bg * BPC;
    const int r0  = rg * RPC;
    const int o0  = rg * OPC;
    unsigned* flg0 = g_flag[bg][0];
    unsigned* flg1 = g_flag[bg][1];

    const uint32_t uX0 = (uint32_t)__cvta_generic_to_shared(sX0);
    const uint32_t uX1 = (uint32_t)__cvta_generic_to_shared(sX1);
    const uint32_t uH  = (uint32_t)__cvta_generic_to_shared(sH);
    const float* sXs[2] = {sX0, sX1};
    const uint32_t uXs[2] = {uX0, uX1};

    const int st_bb = tid >> 5;            // 0..7
    const int st_c  = (tid & 31) * 4;      // 0..124

    // ---- Prologue staging ----
    // Gx: x(0)->slot0, x(1)->slot1
    stage_x(uX0, x, b0, 0, st_bb, st_c);
    stage_x(uX1, x, b0, 1, st_bb, st_c);
    CP_COMMIT();
    // G1: h0(-1) zeros
    stage_h<0>(uH, &g_h0[1][0][0], b0, st_bb, st_c);
    CP_COMMIT();
    // G2: h1(-1) zeros
    stage_h<512>(uH, &g_h1[1][0][0], b0, st_bb, st_c);
    CP_COMMIT();

    // ---- Weights into SMEM (once) ----
    for (int idx = tid; idx < RPC * 768; idx += NTHR) {
        int r = idx / 768, c = idx % 768;
        float v = (c < IN_SZ) ? Win0[(r0 + r) * IN_SZ + c]
                              : Wrec0[(r0 + r) * H_SZ + (c - IN_SZ)];
        sW0[r * P0 + c] = v;
    }
    for (int idx = tid; idx < RPC * 1024; idx += NTHR) {
        int r = idx >> 10, c = idx & 1023;
        float v = (c < H_SZ) ? Win1[(r0 + r) * H_SZ + c]
                             : Wrec1[(r0 + r) * H_SZ + (c - H_SZ)];
        sW1[r * P1 + c] = v;
    }
    for (int idx = tid; idx < OPC * H_SZ; idx += NTHR) {
        int r = idx >> 9, c = idx & 511;
        sWo[r * POW + c] = Wout[(o0 + r) * H_SZ + c];
    }
    if (tid < RPC) {
        sBi0[tid] = bin0[r0 + tid];
        float tc = fminf(fmaxf(tau0[r0 + tid], 0.1f), 10.f);
        sIT0[tid] = DT_C / tc;
        sBi1[tid] = bin1[r0 + tid];
        tc = fminf(fmaxf(tau1[r0 + tid], 0.1f), 10.f);
        sIT1[tid] = DT_C / tc;
    }
    if (tid < OPC) sBo[tid] = bout[o0 + tid];

    // A/B decode
    const int rt    = tid & 3;
    const int bt    = (tid >> 2) & 1;
    const int ksl   = (tid >> 3) & 3;
    const int wrp   = tid >> 5;
    const int ksg   = wrp * 4 + ksl;
    const int rbase = rt * 4;
    const int bbase = bt * 4;
    const int kx = wrp * 32 + ksl * 4;   // x-part (256)
    const int kh = wrp * 64 + ksl * 4;   // h-halves (512)
    // C decode
    const int rtC = tid & 1, btC = (tid >> 1) & 1;
    const int ksgC = tid >> 2;
    const int kbC = wrp * 64 + ((tid >> 2) & 7) * 4;

    // ---- Prologue compute: A-x(0) from slot0 ----
    CP_WAIT(2);              // Gx done (G1,G2 may fly)
    __syncthreads();
    ull accA[4][4] = {};
    mm44p2<2, 16, P0, PX>(sW0, rbase, kx, sX0, bbase, kx, accA);

    // ===================== main loop =====================
    // iter t: A(t)->h0(t), B(t-1)->h1(t-1), C(t-2)->out(t-2); split flags.
    for (int t = 0; t < T_LEN; t++) {
        const int s0i = t & 1;
        const int s1i = s0i ^ 1;
        const unsigned ph = (unsigned)(t + 1);

        // (1) h0(t-1) group landed
        CP_WAIT(1);
        __syncthreads();

        // (2) A-h GEMM + A partial store
        mm44p2<4, 16, P0, PH>(sW0, rbase, 256 + kh, sH, bbase, kh, accA);
#pragma unroll
        for (int i = 0; i < 4; i++)
#pragma unroll
            for (int j = 0; j < 4; j++)
                sRedA[(64 * bt + 16 * j + 4 * rt + i) * 33 + ksg] = x2sum(accA[i][j]);

        // (3) h1(t-2) + x(t+1) groups landed
        CP_WAIT(0);
        __syncthreads();

        // (4) A-reduce -> h0(t)  ||  B(t-1) GEMM + store
        if (tid < 128) {
            float sum = sum32(&sRedA[tid * 33]) + sBi0[tid & 15];
            float tgt = tanhf(sum);
            float hold = sH[(tid >> 4) * PH + r0 + (tid & 15)];        // h0(t-1)
            g_h0[s0i][b0 + (tid >> 4)][r0 + (tid & 15)] = hold + (tgt - hold) * sIT0[tid & 15];
        }
        {
            ull accB[4][4] = {};
            mm44p2<4, 16, P1, PH>(sW1, rbase, kh, sH, bbase, kh, accB);
            mm44p2<4, 16, P1, PH>(sW1, rbase, 512 + kh, sH, bbase, 512 + kh, accB);
#pragma unroll
            for (int i = 0; i < 4; i++)
#pragma unroll
                for (int j = 0; j < 4; j++)
                    sRedB[(64 * bt + 16 * j + 4 * rt + i) * 33 + ksg] = x2sum(accB[i][j]);
        }
        __syncthreads();
        pod_arrive(flg0, rg, ph);                    // publish h0(t) EARLY

        // (5) B-reduce -> h1(t-1)  ||  C(t-2) GEMM + store
        if (t && tid < 128) {
            float sum = sum32(&sRedB[tid * 33]) + sBi1[tid & 15];
            float tgt = tanhf(sum);
            float hold = sH[(tid >> 4) * PH + 512 + r0 + (tid & 15)];  // h1(t-2)
            g_h1[s1i][b0 + (tid >> 4)][r0 + (tid & 15)] = hold + (tgt - hold) * sIT1[tid & 15];
        }
        if (t >= 2) {
            ull accC[4][4] = {};
            mm44p2<2, 32, POW, PH>(sWo, rtC * 4, kbC, sH, btC * 4, 512 + kbC, accC);
#pragma unroll
            for (int i = 0; i < 4; i++)
#pragma unroll
                for (int j = 0; j < 4; j++)
                    sRedC[(32 * btC + 8 * j + 4 * rtC + i) * 65 + ksgC] = x2sum(accC[i][j]);
        }
        __syncthreads();
        pod_arrive(flg1, rg, ph);                    // publish h1(t-1)

        // (6) spin0 (near-instant); stage h0(t) -> sH[0:512]
        pod_spin_w0(flg0, ph);
        __syncthreads();
        stage_h<0>(uH, &g_h0[s0i][0][0], b0, st_bb, st_c);
        CP_COMMIT();                                 // G1'

        // (7) flag1 window: emit out(t-2); A-x(t+1) from slot (t+1)&1
        if (t >= 2 && tid >= 128 && tid < 192) {
            const int rw = tid - 128;
            const int cb = rw >> 3, co = rw & 7;
            float res = __ldg(&x[((size_t)(b0 + cb) * T_LEN + (t - 2)) * IN_SZ + o0 + co]);
            out[((size_t)(b0 + cb) * T_LEN + (t - 2)) * OUT_SZ + o0 + co]
                = sum64(&sRedC[rw * 65]) + sBo[co] + res;
        }
#pragma unroll
        for (int i = 0; i < 4; i++)
#pragma unroll
            for (int j = 0; j < 4; j++)
                accA[i][j] = 0ull;
        if (t + 1 < T_LEN) {
            // x(t+1): t=0 -> prologue slot1; t>=1 -> staged at (8) of t-1,
            // waited at (3)+sync of t. Always valid.
            mm44p2<2, 16, P0, PX>(sW0, rbase, kx, sXs[s1i], bbase, kx, accA);
        }

        // (8) spin1; stage h1(t-1) -> sH[512:], x(t+2) -> slot t&1
        pod_spin_w0(flg1, ph);
        __syncthreads();
        stage_h<512>(uH, &g_h1[s1i][0][0], b0, st_bb, st_c);
        if (t + 2 < T_LEN) {
            stage_x(uXs[s0i], x, b0, t + 2, st_bb, st_c);
        }
        CP_COMMIT();                                 // G2'
    }

    // ===== Epilogue: B(T-1) -> h1(T-1); C(T-2); C(T-1) =====
    CP_WAIT(0);
    __syncthreads();                                 // sH = h0(T-1), h1(T-2)
    {
        ull accB[4][4] = {};
        mm44p2<4, 16, P1, PH>(sW1, rbase, kh, sH, bbase, kh, accB);
        mm44p2<4, 16, P1, PH>(sW1, rbase, 512 + kh, sH, bbase, 512 + kh, accB);
#pragma unroll
        for (int i = 0; i < 4; i++)
#pragma unroll
            for (int j = 0; j < 4; j++)
                sRedB[(64 * bt + 16 * j + 4 * rt + i) * 33 + ksg] = x2sum(accB[i][j]);
    }
    __syncthreads();
    if (tid < 128) {
        float sum = sum32(&sRedB[tid * 33]) + sBi1[tid & 15];
        float tgt = tanhf(sum);
        float hold = sH[(tid >> 4) * PH + 512 + r0 + (tid & 15)];      // h1(T-2)
        g_h1[1][b0 + (tid >> 4)][r0 + (tid & 15)] = hold + (tgt - hold) * sIT1[tid & 15];
    }
    {
        ull accC[4][4] = {};                          // C(T-2)
        mm44p2<2, 32, POW, PH>(sWo, rtC * 4, kbC, sH, btC * 4, 512 + kbC, accC);
#pragma unroll
        for (int i = 0; i < 4; i++)
#pragma unroll
            for (int j = 0; j < 4; j++)
                sRedC[(32 * btC + 8 * j + 4 * rtC + i) * 65 + ksgC] = x2sum(accC[i][j]);
    }
    __syncthreads();
    pod_arrive(flg1, rg, (unsigned)(T_LEN + 1));
    if (tid >= 128 && tid < 192) {
        const int rw = tid - 128;
        const int cb = rw >> 3, co = rw & 7;
        float res = __ldg(&x[((size_t)(b0 + cb) * T_LEN + (T_LEN - 2)) * IN_SZ + o0 + co]);
        out[((size_t)(b0 + cb) * T_LEN + (T_LEN - 2)) * OUT_SZ + o0 + co]
            = sum64(&sRedC[rw * 65]) + sBo[co] + res;
    }
    pod_spin_w0(flg1, (unsigned)(T_LEN + 1));
    __syncthreads();

    stage_h<512>(uH, &g_h1[1][0][0], b0, st_bb, st_c);
    CP_COMMIT();
    CP_WAIT(0);
    __syncthreads();
    {
        ull accC[4][4] = {};                          // C(T-1)
        mm44p2<2, 32, POW, PH>(sWo, rtC * 4, kbC, sH, btC * 4, 512 + kbC, accC);
#pragma unroll
        for (int i = 0; i < 4; i++)
#pragma unroll
            for (int j = 0; j < 4; j++)
                sRedC[(32 * btC + 8 * j + 4 * rtC + i) * 65 + ksgC] = x2sum(accC[i][j]);
    }
    __syncthreads();
    if (tid < 64) {
        const int eb = tid >> 3, eo = tid & 7;
        float res = __ldg(&x[((size_t)(b0 + eb) * T_LEN + (T_LEN - 1)) * IN_SZ + o0 + eo]);
        out[((size_t)(b0 + eb) * T_LEN + (T_LEN - 1)) * OUT_SZ + o0 + eo]
            = sum64(&sRedC[tid * 65]) + sBo[eo] + res;
    }
}

extern "C" void kernel_launch(void* const* d_in, const int* in_sizes, int n_in,
                              void* d_out, int out_size) {
    const float* x     = (const float*)d_in[0];
    const float* Win0  = (const float*)d_in[1];
    const float* bin0  = (const float*)d_in[2];
    const float* Wrec0 = (const float*)d_in[3];
    const float* tau0  = (const float*)d_in[4];
    const float* Win1  = (const float*)d_in[5];
    const float* bin1  = (const float*)d_in[6];
    const float* Wrec1 = (const float*)d_in[7];
    const float* tau1  = (const float*)d_in[8];
    const float* Wout  = (const float*)d_in[9];
    const float* bout  = (const float*)d_in[10];
    float* outp        = (float*)d_out;

    cudaFuncSetAttribute(rnn_persistent,
                         cudaFuncAttributeMaxDynamicSharedMemorySize, SMEM_BYTES);

    init_state_kernel<<<128, 256>>>();
    rnn_persistent<<<NCTA, NTHR, SMEM_BYTES>>>(x, Win0, bin0, Wrec0, tau0,
                                               Win1, bin1, Wrec1, tau1,
                                               Wout, bout, outp);
}

// round 14
// speedup vs baseline: 1.8595x; 1.0052x over previous
#include <cuda_runtime.h>
#include <math.h>
#include <stdint.h>

#define T_LEN  2048
#define B_SZ   32
#define IN_SZ  256
#define H_SZ   512
#define OUT_SZ 256
#define DT_C   0.1f

#define RGROUPS 32
#define BGROUPS 4
#define NCTA    128
#define RPC     16
#define OPC     8
#define BPC     8
#define NTHR    256

// Pitches (floats), %4==0 and ==4 (mod 32)
#define P0  772
#define P1  1028
#define POW 516
#define PX  260    // per x slot
#define PH  1028   // sH: 512 h0 | 512 h1

#define SMEM_FLOATS (RPC*P0 + RPC*P1 + OPC*POW + 2*BPC*PX + BPC*PH + 4224 + 4224 + 4160 + 72)
#define SMEM_BYTES  (SMEM_FLOATS * 4)

typedef unsigned long long ull;

__device__ float g_h0[2][B_SZ][H_SZ];
__device__ float g_h1[2][B_SZ][H_SZ];
__device__ __align__(128) unsigned g_flag[BGROUPS][2][32];  // [pod][flag0|flag1][cta]

__global__ void init_state_kernel() {
    int i = blockIdx.x * blockDim.x + threadIdx.x;
    const int n = 2 * B_SZ * H_SZ;
    if (i < n) {
        ((float*)g_h0)[i] = 0.0f;
        ((float*)g_h1)[i] = 0.0f;
    }
    if (i < BGROUPS * 2 * 32) ((unsigned*)g_flag)[i] = 0u;
}

__device__ __forceinline__ void cpa16(uint32_t dst, const void* src) {
    asm volatile("cp.async.cg.shared.global [%0], [%1], 16;"
                 :: "r"(dst), "l"(src) : "memory");
}
#define CP_COMMIT() asm volatile("cp.async.commit_group;" ::: "memory")
#define CP_WAIT(n)  asm volatile("cp.async.wait_group %0;" :: "n"(n) : "memory")

template<int COFF>
__device__ __forceinline__ void stage_h(uint32_t uH, const float* __restrict__ g,
                                        int b0, int bb, int c) {
#pragma unroll
    for (int q = 0; q < 4; q++) {
        cpa16(uH + (bb * PH + COFF + c + q * 128) * 4,
              &g[(size_t)(b0 + bb) * H_SZ + c + q * 128]);
    }
}
__device__ __forceinline__ void stage_x(uint32_t uXs, const float* __restrict__ xg,
                                        int b0, int t, int bb, int c) {
    cpa16(uXs + (bb * PX + c) * 4,
          &xg[((size_t)(b0 + bb) * T_LEN + t) * IN_SZ + c]);
    cpa16(uXs + (bb * PX + c + 128) * 4,
          &xg[((size_t)(b0 + bb) * T_LEN + t) * IN_SZ + c + 128]);
}

// --- pod barrier: per-CTA flag slots; warp0 spins, block joins via sync ---
__device__ __forceinline__ void pod_arrive(unsigned* flg, int rg, unsigned ph) {
    if (threadIdx.x == 0) {
        __threadfence();   // release: orders all block threads' prior STGs
        asm volatile("st.relaxed.gpu.global.u32 [%0], %1;"
                     :: "l"(flg + rg), "r"(ph) : "memory");
    }
}
__device__ __forceinline__ void pod_spin_w0(const unsigned* flg, unsigned ph) {
    if (threadIdx.x < 32) {
        unsigned v;
        do {
            asm volatile("ld.acquire.gpu.global.u32 %0, [%1];"
                         : "=r"(v) : "l"(flg + threadIdx.x) : "memory");
        } while (__any_sync(0xffffffffu, v < ph));
    }
}

// packed dual-fp32 FMA (FFMA2)
__device__ __forceinline__ void fmax2(ull& d, ull a, ull b) {
    asm("fma.rn.f32x2 %0, %1, %2, %0;" : "+l"(d) : "l"(a), "l"(b));
}
__device__ __forceinline__ float x2sum(ull v) {
    float lo, hi;
    asm("mov.b64 {%0,%1}, %2;" : "=f"(lo), "=f"(hi) : "l"(v));
    return lo + hi;
}

template<int NIT, int KSTEP, int PW, int PAcc>
__device__ __forceinline__ void mm44p2(const float* __restrict__ sW, int rbase, int wk,
                                       const float* __restrict__ sAct, int bbase, int ak,
                                       ull acc[4][4]) {
#pragma unroll
    for (int it = 0; it < NIT; ++it) {
        ulonglong2 w[4], a[4];
#pragma unroll
        for (int i = 0; i < 4; i++)
            w[i] = *(const ulonglong2*)(sW + (rbase + i) * PW + wk + it * KSTEP);
#pragma unroll
        for (int j = 0; j < 4; j++)
            a[j] = *(const ulonglong2*)(sAct + (bbase + j) * PAcc + ak + it * KSTEP);
#pragma unroll
        for (int i = 0; i < 4; i++)
#pragma unroll
            for (int j = 0; j < 4; j++) {
                fmax2(acc[i][j], w[i].x, a[j].x);
                fmax2(acc[i][j], w[i].y, a[j].y);
            }
    }
}

__device__ __forceinline__ float sum32(const float* p) {
    float s0 = 0.f, s1 = 0.f, s2 = 0.f, s3 = 0.f;
#pragma unroll
    for (int kk = 0; kk < 32; kk += 4) {
        s0 += p[kk]; s1 += p[kk + 1]; s2 += p[kk + 2]; s3 += p[kk + 3];
    }
    return (s0 + s1) + (s2 + s3);
}
__device__ __forceinline__ float sum64(const float* p) {
    float s0 = 0.f, s1 = 0.f, s2 = 0.f, s3 = 0.f;
#pragma unroll
    for (int kk = 0; kk < 64; kk += 4) {
        s0 += p[kk]; s1 += p[kk + 1]; s2 += p[kk + 2]; s3 += p[kk + 3];
    }
    return (s0 + s1) + (s2 + s3);
}

__global__ void __launch_bounds__(NTHR, 1)
rnn_persistent(const float* __restrict__ x,
               const float* __restrict__ Win0, const float* __restrict__ bin0,
               const float* __restrict__ Wrec0, const float* __restrict__ tau0,
               const float* __restrict__ Win1, const float* __restrict__ bin1,
               const float* __restrict__ Wrec1, const float* __restrict__ tau1,
               const float* __restrict__ Wout, const float* __restrict__ bout,
               float* __restrict__ out)
{
    extern __shared__ float sm[];
    float* sW0   = sm;                   // [16][P0]
    float* sW1   = sW0 + RPC * P0;       // [16][P1]
    float* sWo   = sW1 + RPC * P1;       // [8][POW]
    float* sX0   = sWo + OPC * POW;      // [8][PX]  x slot 0 (even t)
    float* sX1   = sX0 + BPC * PX;       // [8][PX]  x slot 1 (odd t)
    float* sH    = sX1 + BPC * PX;       // [8][PH]  h0(t-1) | h1(t-2)
    float* sRedA = sH  + BPC * PH;       // 128*33
    float* sRedB = sRedA + 4224;         // 128*33
    float* sRedC = sRedB + 4224;         // 64*65 (own buffer)
    float* sBi0  = sRedC + 4160;
    float* sIT0  = sBi0 + RPC;
    float* sBi1  = sIT0 + RPC;
    float* sIT1  = sBi1 + RPC;
    float* sBo   = sIT1 + RPC;

    const int tid = threadIdx.x;
    const int rg  = blockIdx.x & (RGROUPS - 1);
    const int bg  = blockIdx.x >> 5;
    const int b0  = bg * BPC;
    const int r0  = rg * RPC;
    const int o0  = rg * OPC;
    unsigned* flg0 = g_flag[bg][0];
    unsigned* flg1 = g_flag[bg][1];

    const uint32_t uX0 = (uint32_t)__cvta_generic_to_shared(sX0);
    const uint32_t uX1 = (uint32_t)__cvta_generic_to_shared(sX1);
    const uint32_t uH  = (uint32_t)__cvta_generic_to_shared(sH);
    const float* sXs[2] = {sX0, sX1};
    const uint32_t uXs[2] = {uX0, uX1};

    const int st_bb = tid >> 5;            // 0..7
    const int st_c  = (tid & 31) * 4;      // 0..124

    // ---- Prologue staging ----
    // Gx: x(0)->slot0, x(1)->slot1
    stage_x(uX0, x, b0, 0, st_bb, st_c);
    stage_x(uX1, x, b0, 1, st_bb, st_c);
    CP_COMMIT();
    // G1: h0(-1) zeros
    stage_h<0>(uH, &g_h0[1][0][0], b0, st_bb, st_c);
    CP_COMMIT();
    // G2: h1(-1) zeros
    stage_h<512>(uH, &g_h1[1][0][0], b0, st_bb, st_c);
    CP_COMMIT();

    // ---- Weights into SMEM (once) ----
    for (int idx = tid; idx < RPC * 768; idx += NTHR) {
        int r = idx / 768, c = idx % 768;
        float v = (c < IN_SZ) ? Win0[(r0 + r) * IN_SZ + c]
                              : Wrec0[(r0 + r) * H_SZ + (c - IN_SZ)];
        sW0[r * P0 + c] = v;
    }
    for (int idx = tid; idx < RPC * 1024; idx += NTHR) {
        int r = idx >> 10, c = idx & 1023;
        float v = (c < H_SZ) ? Win1[(r0 + r) * H_SZ + c]
                             : Wrec1[(r0 + r) * H_SZ + (c - H_SZ)];
        sW1[r * P1 + c] = v;
    }
    for (int idx = tid; idx < OPC * H_SZ; idx += NTHR) {
        int r = idx >> 9, c = idx & 511;
        sWo[r * POW + c] = Wout[(o0 + r) * H_SZ + c];
    }
    if (tid < RPC) {
        sBi0[tid] = bin0[r0 + tid];
        float tc = fminf(fmaxf(tau0[r0 + tid], 0.1f), 10.f);
        sIT0[tid] = DT_C / tc;
        sBi1[tid] = bin1[r0 + tid];
        tc = fminf(fmaxf(tau1[r0 + tid], 0.1f), 10.f);
        sIT1[tid] = DT_C / tc;
    }
    if (tid < OPC) sBo[tid] = bout[o0 + tid];

    // A/B decode
    const int rt    = tid & 3;
    const int bt    = (tid >> 2) & 1;
    const int ksl   = (tid >> 3) & 3;
    const int wrp   = tid >> 5;
    const int ksg   = wrp * 4 + ksl;
    const int rbase = rt * 4;
    const int bbase = bt * 4;
    const int kx = wrp * 32 + ksl * 4;   // x-part (256)
    const int kh = wrp * 64 + ksl * 4;   // h-halves (512)
    // C decode
    const int rtC = tid & 1, btC = (tid >> 1) & 1;
    const int ksgC = tid >> 2;
    const int kbC = wrp * 64 + ((tid >> 2) & 7) * 4;

    // ---- Prologue compute: A-x(0) from slot0 ----
    CP_WAIT(2);              // Gx done (G1,G2 may fly)
    __syncthreads();
    ull accA[4][4] = {};
    mm44p2<2, 16, P0, PX>(sW0, rbase, kx, sX0, bbase, kx, accA);

    // ===================== main loop =====================
    // iter t: A(t)->h0(t), B(t-1)->h1(t-1), C(t-2)->out(t-2); split flags.
    for (int t = 0; t < T_LEN; t++) {
        const int s0i = t & 1;
        const int s1i = s0i ^ 1;
        const unsigned ph = (unsigned)(t + 1);

        // (1) h0(t-1) group landed
        CP_WAIT(1);
        __syncthreads();

        // (2) A-h GEMM + A partial store
        mm44p2<4, 16, P0, PH>(sW0, rbase, 256 + kh, sH, bbase, kh, accA);
#pragma unroll
        for (int i = 0; i < 4; i++)
#pragma unroll
            for (int j = 0; j < 4; j++)
                sRedA[(64 * bt + 16 * j + 4 * rt + i) * 33 + ksg] = x2sum(accA[i][j]);

        // (3) h1(t-2) + x(t+1) groups landed
        CP_WAIT(0);
        __syncthreads();

        // (4) A-reduce -> h0(t)  ||  B(t-1) GEMM + store
        if (tid < 128) {
            float sum = sum32(&sRedA[tid * 33]) + sBi0[tid & 15];
            float tgt = tanhf(sum);
            float hold = sH[(tid >> 4) * PH + r0 + (tid & 15)];        // h0(t-1)
            g_h0[s0i][b0 + (tid >> 4)][r0 + (tid & 15)] = hold + (tgt - hold) * sIT0[tid & 15];
        }
        {
            ull accB[4][4] = {};
            mm44p2<4, 16, P1, PH>(sW1, rbase, kh, sH, bbase, kh, accB);
            mm44p2<4, 16, P1, PH>(sW1, rbase, 512 + kh, sH, bbase, 512 + kh, accB);
#pragma unroll
            for (int i = 0; i < 4; i++)
#pragma unroll
                for (int j = 0; j < 4; j++)
                    sRedB[(64 * bt + 16 * j + 4 * rt + i) * 33 + ksg] = x2sum(accB[i][j]);
        }
        __syncthreads();
        pod_arrive(flg0, rg, ph);                    // publish h0(t) EARLY

        // (5) B-reduce -> h1(t-1)  ||  C(t-2) GEMM + store
        if (t && tid < 128) {
            float sum = sum32(&sRedB[tid * 33]) + sBi1[tid & 15];
            float tgt = tanhf(sum);
            float hold = sH[(tid >> 4) * PH + 512 + r0 + (tid & 15)];  // h1(t-2)
            g_h1[s1i][b0 + (tid >> 4)][r0 + (tid & 15)] = hold + (tgt - hold) * sIT1[tid & 15];
        }
        if (t >= 2) {
            ull accC[4][4] = {};
            mm44p2<2, 32, POW, PH>(sWo, rtC * 4, kbC, sH, btC * 4, 512 + kbC, accC);
#pragma unroll
            for (int i = 0; i < 4; i++)
#pragma unroll
                for (int j = 0; j < 4; j++)
                    sRedC[(32 * btC + 8 * j + 4 * rtC + i) * 65 + ksgC] = x2sum(accC[i][j]);
        }
        __syncthreads();
        pod_arrive(flg1, rg, ph);                    // publish h1(t-1)

        // (6) spin0 (near-instant); stage h0(t) -> sH[0:512]
        pod_spin_w0(flg0, ph);
        __syncthreads();
        stage_h<0>(uH, &g_h0[s0i][0][0], b0, st_bb, st_c);
        CP_COMMIT();                                 // G1'

        // (7) flag1 window: emit out(t-2); A-x(t+1) from slot (t+1)&1
        if (t >= 2 && tid >= 128 && tid < 192) {
            const int rw = tid - 128;
            const int cb = rw >> 3, co = rw & 7;
            float res = __ldg(&x[((size_t)(b0 + cb) * T_LEN + (t - 2)) * IN_SZ + o0 + co]);
            out[((size_t)(b0 + cb) * T_LEN + (t - 2)) * OUT_SZ + o0 + co]
                = sum64(&sRedC[rw * 65]) + sBo[co] + res;
        }
#pragma unroll
        for (int i = 0; i < 4; i++)
#pragma unroll
            for (int j = 0; j < 4; j++)
                accA[i][j] = 0ull;
        if (t + 1 < T_LEN) {
            // x(t+1): t=0 -> prologue slot1; t>=1 -> staged at (8) of t-1,
            // waited at (3)+sync of t. Always valid.
            mm44p2<2, 16, P0, PX>(sW0, rbase, kx, sXs[s1i], bbase, kx, accA);
        }

        // (8) spin1; stage h1(t-1) -> sH[512:], x(t+2) -> slot t&1
        pod_spin_w0(flg1, ph);
        __syncthreads();
        stage_h<512>(uH, &g_h1[s1i][0][0], b0, st_bb, st_c);
        if (t + 2 < T_LEN) {
            stage_x(uXs[s0i], x, b0, t + 2, st_bb, st_c);
        }
        CP_COMMIT();                                 // G2'
    }

    // ===== Epilogue: B(T-1) -> h1(T-1); C(T-2); C(T-1) =====
    CP_WAIT(0);
    __syncthreads();                                 // sH = h0(T-1), h1(T-2)
    {
        ull accB[4][4] = {};
        mm44p2<4, 16, P1, PH>(sW1, rbase, kh, sH, bbase, kh, accB);
        mm44p2<4, 16, P1, PH>(sW1, rbase, 512 + kh, sH, bbase, 512 + kh, accB);
#pragma unroll
        for (int i = 0; i < 4; i++)
#pragma unroll
            for (int j = 0; j < 4; j++)
                sRedB[(64 * bt + 16 * j + 4 * rt + i) * 33 + ksg] = x2sum(accB[i][j]);
    }
    __syncthreads();
    if (tid < 128) {
        float sum = sum32(&sRedB[tid * 33]) + sBi1[tid & 15];
        float tgt = tanhf(sum);
        float hold = sH[(tid >> 4) * PH + 512 + r0 + (tid & 15)];      // h1(T-2)
        g_h1[1][b0 + (tid >> 4)][r0 + (tid & 15)] = hold + (tgt - hold) * sIT1[tid & 15];
    }
    {
        ull accC[4][4] = {};                          // C(T-2)
        mm44p2<2, 32, POW, PH>(sWo, rtC * 4, kbC, sH, btC * 4, 512 + kbC, accC);
#pragma unroll
        for (int i = 0; i < 4; i++)
#pragma unroll
            for (int j = 0; j < 4; j++)
                sRedC[(32 * btC + 8 * j + 4 * rtC + i) * 65 + ksgC] = x2sum(accC[i][j]);
    }
    __syncthreads();
    pod_arrive(flg1, rg, (unsigned)(T_LEN + 1));
    if (tid >= 128 && tid < 192) {
        const int rw = tid - 128;
        const int cb = rw >> 3, co = rw & 7;
        float res = __ldg(&x[((size_t)(b0 + cb) * T_LEN + (T_LEN - 2)) * IN_SZ + o0 + co]);
        out[((size_t)(b0 + cb) * T_LEN + (T_LEN - 2)) * OUT_SZ + o0 + co]
            = sum64(&sRedC[rw * 65]) + sBo[co] + res;
    }
    pod_spin_w0(flg1, (unsigned)(T_LEN + 1));
    __syncthreads();

    stage_h<512>(uH, &g_h1[1][0][0], b0, st_bb, st_c);
    CP_COMMIT();
    CP_WAIT(0);
    __syncthreads();
    {
        ull accC[4][4] = {};                          // C(T-1)
        mm44p2<2, 32, POW, PH>(sWo, rtC * 4, kbC, sH, btC * 4, 512 + kbC, accC);
#pragma unroll
        for (int i = 0; i < 4; i++)
#pragma unroll
            for (int j = 0; j < 4; j++)
                sRedC[(32 * btC + 8 * j + 4 * rtC + i) * 65 + ksgC] = x2sum(accC[i][j]);
    }
    __syncthreads();
    if (tid < 64) {
        const int eb = tid >> 3, eo = tid & 7;
        float res = __ldg(&x[((size_t)(b0 + eb) * T_LEN + (T_LEN - 1)) * IN_SZ + o0 + eo]);
        out[((size_t)(b0 + eb) * T_LEN + (T_LEN - 1)) * OUT_SZ + o0 + eo]
            = sum64(&sRedC[tid * 65]) + sBo[eo] + res;
    }
}

extern "C" void kernel_launch(void* const* d_in, const int* in_sizes, int n_in,
                              void* d_out, int out_size) {
    const float* x     = (const float*)d_in[0];
    const float* Win0  = (const float*)d_in[1];
    const float* bin0  = (const float*)d_in[2];
    const float* Wrec0 = (const float*)d_in[3];
    const float* tau0  = (const float*)d_in[4];
    const float* Win1  = (const float*)d_in[5];
    const float* bin1  = (const float*)d_in[6];
    const float* Wrec1 = (const float*)d_in[7];
    const float* tau1  = (const float*)d_in[8];
    const float* Wout  = (const float*)d_in[9];
    const float* bout  = (const float*)d_in[10];
    float* outp        = (float*)d_out;

    cudaFuncSetAttribute(rnn_persistent,
                         cudaFuncAttributeMaxDynamicSharedMemorySize, SMEM_BYTES);

    init_state_kernel<<<128, 256>>>();
    rnn_persistent<<<NCTA, NTHR, SMEM_BYTES>>>(x, Win0, bin0, Wrec0, tau0,
                                               Win1, bin1, Wrec1, tau1,
                                               Wout, bout, outp);
}